// round 6
// baseline (speedup 1.0000x reference)
#include <cuda_runtime.h>
#include <math.h>

#define MDIM 4096
#define NT 32            // 32 tile-rows of 128
#define TILE 128
#define NBLK 528         // upper triangle: 32*33/2 tiles, 1 block each
#define B1f 0.9f
#define B2f 0.999f
#define EPSV 1e-8f
#define LRV 0.1f
#define NSTEPS 199

// ---- scratch (__device__ globals; no allocation) ----
__device__ float d_Qs[(size_t)MDIM * MDIM];      // symmetrized fp32 (upper half valid)
__device__ float d_g[(NSTEPS + 1)][MDIM];        // per-step g buffers (g[0] stays 0)
__device__ float d_W[2][MDIM];                   // parity-buffered Adam state
__device__ float d_MT[2][MDIM];
__device__ float d_VT[2][MDIM];
__device__ float d_steplr[NSTEPS + 1];           // LR/bc1(t), t=0..199 ([0]=0)
__device__ float d_invb2[NSTEPS + 1];            // 1/sqrt(bc2(t))       ([0]=0)
__device__ unsigned int d_barcnt;

// ---------------------------------------------------------------------------
__global__ void prep_qs_kernel(const float* __restrict__ va) {
    __shared__ float tile[32][33];
    int bx = blockIdx.x * 32, by = blockIdx.y * 32;
    if (bx + 32 <= by) return;                   // upper-triangle blocks only
    int tx = threadIdx.x, ty = threadIdx.y;
    tile[ty][tx] = va[(size_t)(bx + ty) * MDIM + (by + tx)];
    __syncthreads();
    size_t idx = (size_t)(by + ty) * MDIM + (bx + tx);
    d_Qs[idx] = 0.5f * (va[idx] + tile[tx][ty]);
}

// ---------------------------------------------------------------------------
__global__ void init_kernel() {
    int i = blockIdx.x * blockDim.x + threadIdx.x;
    if (i < MDIM) {
        d_W[0][i] = 1.0f;  d_W[1][i] = 1.0f;
        d_MT[0][i] = 0.0f; d_MT[1][i] = 0.0f;
        d_VT[0][i] = 0.0f; d_VT[1][i] = 0.0f;
    }
    if (i == 0) d_barcnt = 0u;
    if (i <= NSTEPS) {
        if (i == 0) { d_steplr[0] = 0.0f; d_invb2[0] = 0.0f; }
        else {
            double bc1 = 1.0 - pow(0.9,   (double)i);
            double bc2 = 1.0 - pow(0.999, (double)i);
            d_steplr[i] = (float)((double)LRV / bc1);
            d_invb2[i]  = (float)(1.0 / sqrt(bc2));
        }
    }
    int total = (NSTEPS + 1) * MDIM;
    for (int j = i; j < total; j += gridDim.x * blockDim.x)
        (&d_g[0][0])[j] = 0.0f;
}

// ---------------------------------------------------------------------------
// Persistent kernel: 528 co-resident blocks, 199 steps, grid barrier/step.
// ---------------------------------------------------------------------------
__global__ __launch_bounds__(256, 4)
void persist_kernel(const float* __restrict__ mean,
                    float* __restrict__ out,
                    float* __restrict__ g_base)
{
    __shared__ float xsI[TILE];
    __shared__ float xsJ[TILE];
    __shared__ float part[TILE][33];
    __shared__ float colp[8][TILE];

    // block -> upper-triangle tile (ti <= tj)
    int b = blockIdx.x;
    int ti = 0, rem = b;
    while (rem >= NT - ti) { rem -= NT - ti; ++ti; }
    int tj = ti + rem;
    const int I = ti * TILE, J = tj * TILE;
    const bool diag = (ti == tj);

    int tid = threadIdx.x, warp = tid >> 5, lane = tid & 31;
    const float4* __restrict__ Q4 = reinterpret_cast<const float4*>(d_Qs);
    size_t qbase = (size_t)(I + warp * 16) * (MDIM / 4) + (J / 4) + lane;

    for (int s = 1; s <= NSTEPS; ++s) {
        int t = s - 1;
        int p = t & 1, q = p ^ 1;
        float steplr = d_steplr[t];
        float invb2  = d_invb2[t];
        const float* g_prev = g_base + (size_t)t * MDIM;
        float*       g_out  = g_base + (size_t)s * MDIM;

        // ---- prologue: duplicated Adam step t, build x (L2-coherent reads) ----
        {
            int row = -1;
            if (diag) { if (tid < TILE) row = I + tid; }
            else      { row = (tid < TILE) ? (I + tid) : (J + tid - TILE); }
            if (row >= 0) {
                float g  = __ldcg(&g_prev[row]);
                float mt = B1f * __ldcg(&d_MT[p][row]) + (1.0f - B1f) * g;
                float vt = B2f * __ldcg(&d_VT[p][row]) + (1.0f - B2f) * g * g;
                float wn = __ldcg(&d_W[p][row])
                         - steplr * mt / (sqrtf(vt) * invb2 + EPSV);
                d_W[q][row]  = wn;
                d_MT[q][row] = mt;
                d_VT[q][row] = vt;
                float x = wn - mean[row];
                if (tid < TILE) { xsI[tid] = x; if (diag) xsJ[tid] = x; }
                else            { xsJ[tid - TILE] = x; }
            }
        }
        __syncthreads();

        // ---- SYMV tile: warp owns 16 rows; lane owns one float4 col chunk ----
        float4 xj = reinterpret_cast<const float4*>(xsJ)[lane];
        float  rp[16];
        float4 ca = make_float4(0.f, 0.f, 0.f, 0.f);

        if (!diag) {
            #pragma unroll
            for (int rr = 0; rr < 16; rr += 8) {
                float4 qv[8];
                #pragma unroll
                for (int k = 0; k < 8; ++k)
                    qv[k] = Q4[qbase + (size_t)(rr + k) * (MDIM / 4)];
                #pragma unroll
                for (int k = 0; k < 8; ++k) {
                    float xi = xsI[warp * 16 + rr + k];
                    rp[rr + k] = qv[k].x * xj.x + qv[k].y * xj.y
                               + qv[k].z * xj.z + qv[k].w * xj.w;
                    ca.x = fmaf(qv[k].x, xi, ca.x);
                    ca.y = fmaf(qv[k].y, xi, ca.y);
                    ca.z = fmaf(qv[k].z, xi, ca.z);
                    ca.w = fmaf(qv[k].w, xi, ca.w);
                }
            }
        } else {
            int c0 = 4 * lane;
            #pragma unroll
            for (int rr = 0; rr < 16; rr += 8) {
                float4 qv[8];
                #pragma unroll
                for (int k = 0; k < 8; ++k)
                    qv[k] = Q4[qbase + (size_t)(rr + k) * (MDIM / 4)];
                #pragma unroll
                for (int k = 0; k < 8; ++k) {
                    int lr = warp * 16 + rr + k;
                    float xi = xsI[lr];
                    float r0 = (c0 + 0 >= lr) ? qv[k].x * xj.x : 0.f;
                    float r1 = (c0 + 1 >= lr) ? qv[k].y * xj.y : 0.f;
                    float r2 = (c0 + 2 >= lr) ? qv[k].z * xj.z : 0.f;
                    float r3 = (c0 + 3 >= lr) ? qv[k].w * xj.w : 0.f;
                    rp[rr + k] = (r0 + r1) + (r2 + r3);
                    if (c0 + 0 > lr) ca.x = fmaf(qv[k].x, xi, ca.x);
                    if (c0 + 1 > lr) ca.y = fmaf(qv[k].y, xi, ca.y);
                    if (c0 + 2 > lr) ca.z = fmaf(qv[k].z, xi, ca.z);
                    if (c0 + 3 > lr) ca.w = fmaf(qv[k].w, xi, ca.w);
                }
            }
        }

        #pragma unroll
        for (int k = 0; k < 16; ++k)
            part[warp * 16 + k][lane] = rp[k];
        reinterpret_cast<float4*>(colp[warp])[lane] = ca;
        __syncthreads();

        // ---- reduce + flush (col flush ALSO for diag: mirror terms) ----
        if (tid < TILE) {
            float acc = 0.f;
            #pragma unroll
            for (int l = 0; l < 32; ++l) acc += part[tid][l];
            atomicAdd(&g_out[I + tid], acc);
        } else {
            int c = tid - TILE;
            float acc = 0.f;
            #pragma unroll
            for (int w = 0; w < 8; ++w) acc += colp[w][c];
            atomicAdd(&g_out[J + c], acc);
        }
        __threadfence();
        __syncthreads();

        // ---- grid barrier (cumulative counter; reset by init each replay) ----
        if (tid == 0) {
            atomicAdd(&d_barcnt, 1u);
            unsigned target = (unsigned)s * NBLK;
            while (*(volatile unsigned int*)&d_barcnt < target) { }
        }
        __syncthreads();
    }

    // ---- final Adam step t=199 -> out (state parity 1) ----
    {
        float steplr = d_steplr[NSTEPS];
        float invb2  = d_invb2[NSTEPS];
        const float* g_last = g_base + (size_t)NSTEPS * MDIM;
        int gid = blockIdx.x * 256 + tid;
        if (gid < MDIM) {
            float g  = __ldcg(&g_last[gid]);
            float mt = B1f * __ldcg(&d_MT[1][gid]) + (1.0f - B1f) * g;
            float vt = B2f * __ldcg(&d_VT[1][gid]) + (1.0f - B2f) * g * g;
            out[gid] = __ldcg(&d_W[1][gid])
                     - steplr * mt / (sqrtf(vt) * invb2 + EPSV);
        }
    }
}

// ---------------------------------------------------------------------------
extern "C" void kernel_launch(void* const* d_in, const int* in_sizes, int n_in,
                              void* d_out, int out_size) {
    const float* mean = (const float*)d_in[0];
    const float* va   = (const float*)d_in[1];
    float* out = (float*)d_out;
    (void)in_sizes; (void)n_in; (void)out_size;

    float* g_base; cudaGetSymbolAddress((void**)&g_base, d_g);

    dim3 tb(32, 32), tg(MDIM / 32, MDIM / 32);
    prep_qs_kernel<<<tg, tb>>>(va);
    init_kernel<<<128, 256>>>();
    persist_kernel<<<NBLK, 256>>>(mean, out, g_base);
}